// round 2
// baseline (speedup 1.0000x reference)
#include <cuda_runtime.h>

#define T_ 256
#define D_ 64
#define H_ 256
#define B_ 512
#define ROWS 4
#define NCTA (B_ / ROWS)   // 128 CTAs

__device__ float g_dt[T_];

__global__ void prep_dt_kernel(const float* __restrict__ tps) {
    int t = threadIdx.x;
    if (t < T_) {
        if (t == 0) {
            // match jnp.diff(tps, prepend=tps[:1]-0.01) in fp32 exactly
            g_dt[0] = tps[0] - (tps[0] - 0.01f);
        } else {
            g_dt[t] = tps[t] - tps[t - 1];
        }
    }
}

__device__ __forceinline__ float sigmoidf_(float v) {
    return 1.0f / (1.0f + expf(-v));
}

__device__ __forceinline__ float dot4(float4 a, float4 b) {
    return a.x * b.x + a.y * b.y + a.z * b.z + a.w * b.w;
}

__global__ __launch_bounds__(H_, 1)
void gruode_kernel(const float* __restrict__ x,
                   const float* __restrict__ mask,
                   const float* __restrict__ w_ih,
                   const float* __restrict__ w_hh,
                   const float* __restrict__ b_ih,
                   const float* __restrict__ b_hh,
                   const float* __restrict__ w1,
                   const float* __restrict__ b1,
                   const float* __restrict__ w2,
                   const float* __restrict__ b2,
                   const float* __restrict__ w_out,
                   const float* __restrict__ b_out,
                   float* __restrict__ out)
{
    __shared__ float sh[ROWS][H_];    // h
    __shared__ float sode[ROWS][H_];  // h_ode
    __shared__ float sa1[ROWS][H_];   // tanh(h@w1^T+b1)
    __shared__ float sx[ROWS][D_];    // x_t
    __shared__ float smk[ROWS];       // mask_t

    const int j = threadIdx.x;
    const int row0 = blockIdx.x * ROWS;

    #pragma unroll
    for (int r = 0; r < ROWS; r++) sh[r][j] = 0.0f;

    float hlast[ROWS];
    float seen[ROWS];
    #pragma unroll
    for (int r = 0; r < ROWS; r++) { hlast[r] = 0.0f; seen[r] = 0.0f; }

    const float b1j = b1[j];
    const float b2j = b2[j];
    const float bir = b_ih[j], biz = b_ih[H_ + j], bin_ = b_ih[2 * H_ + j];
    const float bhr = b_hh[j], bhz = b_hh[H_ + j], bhn = b_hh[2 * H_ + j];

    // Each thread's weight rows are contiguous in memory (row-major [out][in])
    const float4* __restrict__ w1r = reinterpret_cast<const float4*>(w1 + (size_t)j * H_);
    const float4* __restrict__ w2r = reinterpret_cast<const float4*>(w2 + (size_t)j * H_);
    const float4* __restrict__ whr = reinterpret_cast<const float4*>(w_hh + (size_t)j * H_);
    const float4* __restrict__ whz = reinterpret_cast<const float4*>(w_hh + (size_t)(H_ + j) * H_);
    const float4* __restrict__ whn = reinterpret_cast<const float4*>(w_hh + (size_t)(2 * H_ + j) * H_);
    const float4* __restrict__ wirp = reinterpret_cast<const float4*>(w_ih + (size_t)j * D_);
    const float4* __restrict__ wizp = reinterpret_cast<const float4*>(w_ih + (size_t)(H_ + j) * D_);
    const float4* __restrict__ winp = reinterpret_cast<const float4*>(w_ih + (size_t)(2 * H_ + j) * D_);

    __syncthreads();

    for (int t = 0; t < T_; t++) {
        // ---- load x_t (4 rows x 64) and mask_t ----
        {
            int r = j >> 6, c = j & 63;
            sx[r][c] = x[((size_t)(row0 + r) * T_ + t) * D_ + c];
        }
        if (j < ROWS) smk[j] = mask[(size_t)(row0 + j) * T_ + t];
        __syncthreads();

        const float dtv = g_dt[t];

        // ---- a1 = tanh(h @ w1^T + b1) ----
        {
            float acc[ROWS];
            #pragma unroll
            for (int r = 0; r < ROWS; r++) acc[r] = b1j;
            #pragma unroll 4
            for (int k = 0; k < H_ / 4; k++) {
                float4 w = w1r[k];
                #pragma unroll
                for (int r = 0; r < ROWS; r++) {
                    float4 hv = *reinterpret_cast<const float4*>(&sh[r][4 * k]);
                    acc[r] += dot4(hv, w);
                }
            }
            #pragma unroll
            for (int r = 0; r < ROWS; r++) sa1[r][j] = tanhf(acc[r]);
        }
        __syncthreads();

        // ---- f = a1 @ w2^T + b2 ; euler ; h_ode ----
        {
            float acc[ROWS];
            #pragma unroll
            for (int r = 0; r < ROWS; r++) acc[r] = b2j;
            #pragma unroll 4
            for (int k = 0; k < H_ / 4; k++) {
                float4 w = w2r[k];
                #pragma unroll
                for (int r = 0; r < ROWS; r++) {
                    float4 av = *reinterpret_cast<const float4*>(&sa1[r][4 * k]);
                    acc[r] += dot4(av, w);
                }
            }
            #pragma unroll
            for (int r = 0; r < ROWS; r++) {
                float hc = sh[r][j];
                float he = hc + dtv * acc[r];
                sode[r][j] = (seen[r] > 0.0f) ? he : hc;
            }
        }
        __syncthreads();

        // ---- gates: gi = x_t @ w_ih^T + b_ih ; gh = h_ode @ w_hh^T + b_hh ----
        {
            float ir[ROWS], iz[ROWS], inn[ROWS];
            #pragma unroll
            for (int r = 0; r < ROWS; r++) { ir[r] = bir; iz[r] = biz; inn[r] = bin_; }
            #pragma unroll
            for (int k = 0; k < D_ / 4; k++) {
                float4 wr = wirp[k];
                float4 wz = wizp[k];
                float4 wn = winp[k];
                #pragma unroll
                for (int r = 0; r < ROWS; r++) {
                    float4 xv = *reinterpret_cast<const float4*>(&sx[r][4 * k]);
                    ir[r] += dot4(xv, wr);
                    iz[r] += dot4(xv, wz);
                    inn[r] += dot4(xv, wn);
                }
            }

            float gr[ROWS], gz[ROWS], gn[ROWS];
            #pragma unroll
            for (int r = 0; r < ROWS; r++) { gr[r] = bhr; gz[r] = bhz; gn[r] = bhn; }
            #pragma unroll 2
            for (int k = 0; k < H_ / 4; k++) {
                float4 wr = whr[k];
                float4 wz = whz[k];
                float4 wn = whn[k];
                #pragma unroll
                for (int r = 0; r < ROWS; r++) {
                    float4 hv = *reinterpret_cast<const float4*>(&sode[r][4 * k]);
                    gr[r] += dot4(hv, wr);
                    gz[r] += dot4(hv, wz);
                    gn[r] += dot4(hv, wn);
                }
            }

            #pragma unroll
            for (int r = 0; r < ROWS; r++) {
                float rg = sigmoidf_(ir[r] + gr[r]);
                float zg = sigmoidf_(iz[r] + gz[r]);
                float ng = tanhf(inn[r] + rg * gn[r]);
                float ho = sode[r][j];
                float hrnn = (1.0f - zg) * ng + zg * ho;
                float m = smk[r];
                float hn = (m > 0.5f) ? hrnn : ho;
                sh[r][j] = hn;
                hlast[r] = (m > 0.5f) ? hn : hlast[r];
                seen[r] = fmaxf(seen[r], m);
            }
        }
        __syncthreads();
    }

    // ---- final projection: out = h_last @ w_out^T + b_out ----
    #pragma unroll
    for (int r = 0; r < ROWS; r++) sh[r][j] = hlast[r];
    __syncthreads();

    {
        float acc[ROWS];
        float bo = b_out[j];
        #pragma unroll
        for (int r = 0; r < ROWS; r++) acc[r] = bo;
        const float4* __restrict__ wo = reinterpret_cast<const float4*>(w_out + (size_t)j * H_);
        #pragma unroll 4
        for (int k = 0; k < H_ / 4; k++) {
            float4 w = wo[k];
            #pragma unroll
            for (int r = 0; r < ROWS; r++) {
                float4 hv = *reinterpret_cast<const float4*>(&sh[r][4 * k]);
                acc[r] += dot4(hv, w);
            }
        }
        #pragma unroll
        for (int r = 0; r < ROWS; r++) {
            out[(size_t)(row0 + r) * H_ + j] = acc[r];
        }
    }
}

extern "C" void kernel_launch(void* const* d_in, const int* in_sizes, int n_in,
                              void* d_out, int out_size) {
    const float* x     = (const float*)d_in[0];
    const float* tps   = (const float*)d_in[1];
    const float* mask  = (const float*)d_in[2];
    const float* w_ih  = (const float*)d_in[3];
    const float* w_hh  = (const float*)d_in[4];
    const float* b_ih  = (const float*)d_in[5];
    const float* b_hh  = (const float*)d_in[6];
    const float* w1    = (const float*)d_in[7];
    const float* b1    = (const float*)d_in[8];
    const float* w2    = (const float*)d_in[9];
    const float* b2    = (const float*)d_in[10];
    const float* w_out = (const float*)d_in[11];
    const float* b_out = (const float*)d_in[12];
    float* out = (float*)d_out;

    prep_dt_kernel<<<1, 256>>>(tps);
    gruode_kernel<<<NCTA, H_>>>(x, mask, w_ih, w_hh, b_ih, b_hh,
                                w1, b1, w2, b2, w_out, b_out, out);
}

// round 3
// speedup vs baseline: 1.7458x; 1.7458x over previous
#include <cuda_runtime.h>

#define T_ 256
#define D_ 64
#define H_ 256
#define B_ 512
#define ROWS 8
#define NP (ROWS / 2)          // 4 row-pairs
#define NCTA (B_ / ROWS)       // 64 CTAs

// ---------------- packed weight scratch (device globals, no allocation) ----
// layout: P[k4 * O + o] = float4{ W[o][4k4+0], W[o][4k4+1], W[o][4k4+2], W[o][4k4+3] }
__device__ float4 g_w1p[(H_ / 4) * H_];          // 16384
__device__ float4 g_w2p[(H_ / 4) * H_];          // 16384
__device__ float4 g_whhp[(H_ / 4) * (3 * H_)];   // 49152
__device__ float4 g_wihp[(D_ / 4) * (3 * H_)];   // 12288
__device__ float4 g_woutp[(H_ / 4) * H_];        // 16384
__device__ float g_dt[T_];

#define N_W1 ((H_ / 4) * H_)
#define N_WHH ((H_ / 4) * (3 * H_))
#define N_WIH ((D_ / 4) * (3 * H_))
#define PK_TOTAL (3 * N_W1 + N_WHH + N_WIH)      // 110592

__global__ void pack_all_kernel(const float* __restrict__ w1,
                                const float* __restrict__ w2,
                                const float* __restrict__ whh,
                                const float* __restrict__ wih,
                                const float* __restrict__ wout,
                                const float* __restrict__ tps) {
    int idx = blockIdx.x * blockDim.x + threadIdx.x;
    if (idx < T_) {
        g_dt[idx] = (idx == 0) ? (tps[0] - (tps[0] - 0.01f))
                               : (tps[idx] - tps[idx - 1]);
    }
    if (idx >= PK_TOTAL) return;

    const float* src;
    float4* dst;
    int O, K, local = idx;
    if (local < N_W1) { src = w1; dst = g_w1p; O = H_; K = H_; }
    else if ((local -= N_W1) < N_W1) { src = w2; dst = g_w2p; O = H_; K = H_; }
    else if ((local -= N_W1) < N_WHH) { src = whh; dst = g_whhp; O = 3 * H_; K = H_; }
    else if ((local -= N_WHH) < N_WIH) { src = wih; dst = g_wihp; O = 3 * H_; K = D_; }
    else { local -= N_WIH; src = wout; dst = g_woutp; O = H_; K = H_; }

    int k4 = local / O;
    int o = local % O;
    const float* s = src + (size_t)o * K + 4 * k4;
    dst[local] = make_float4(s[0], s[1], s[2], s[3]);
}

// ---------------- f32x2 packed-math helpers ----------------
__device__ __forceinline__ unsigned long long pk2(float a, float b) {
    unsigned long long r;
    asm("mov.b64 %0, {%1, %2};" : "=l"(r) : "f"(a), "f"(b));
    return r;
}
__device__ __forceinline__ unsigned long long dup2(float a) { return pk2(a, a); }
__device__ __forceinline__ unsigned long long ffma2(unsigned long long a,
                                                    unsigned long long b,
                                                    unsigned long long c) {
    unsigned long long d;
    asm("fma.rn.f32x2 %0, %1, %2, %3;" : "=l"(d) : "l"(a), "l"(b), "l"(c));
    return d;
}
__device__ __forceinline__ float2 upk2(unsigned long long v) {
    float2 f;
    asm("mov.b64 {%0, %1}, %2;" : "=f"(f.x), "=f"(f.y) : "l"(v));
    return f;
}
__device__ __forceinline__ float sigmoidf_(float v) {
    return 1.0f / (1.0f + expf(-v));
}

// Full-H GEMM contribution for 4 row-pairs: acc[p] += sum_k W[j][k]*(pairK)
// hbuf is float2[NP][H_], wp points at packed [k4*H_ + j] layout.
#define GEMM_H(ACC, WP, HBUF)                                              \
    _Pragma("unroll 2")                                                    \
    for (int k4 = 0; k4 < H_ / 4; k4++) {                                  \
        float4 w = (WP)[k4 * H_ + j];                                      \
        unsigned long long w0 = dup2(w.x), w1d = dup2(w.y);                \
        unsigned long long w2d = dup2(w.z), w3d = dup2(w.w);               \
        _Pragma("unroll")                                                  \
        for (int p = 0; p < NP; p++) {                                     \
            ulonglong2 hA = *reinterpret_cast<const ulonglong2*>(&(HBUF)[p][4 * k4]);     \
            ulonglong2 hB = *reinterpret_cast<const ulonglong2*>(&(HBUF)[p][4 * k4 + 2]); \
            (ACC)[p] = ffma2(w0, hA.x, (ACC)[p]);                          \
            (ACC)[p] = ffma2(w1d, hA.y, (ACC)[p]);                         \
            (ACC)[p] = ffma2(w2d, hB.x, (ACC)[p]);                         \
            (ACC)[p] = ffma2(w3d, hB.y, (ACC)[p]);                         \
        }                                                                  \
    }

__global__ void __launch_bounds__(H_, 1)
gruode_kernel(const float* __restrict__ x,
              const float* __restrict__ mask,
              const float* __restrict__ b_ih,
              const float* __restrict__ b_hh,
              const float* __restrict__ b1,
              const float* __restrict__ b2,
              const float* __restrict__ b_out,
              float* __restrict__ out) {
    __shared__ __align__(16) float2 h2[NP][H_];
    __shared__ __align__(16) float2 ode2[NP][H_];
    __shared__ __align__(16) float2 a12[NP][H_];
    __shared__ __align__(16) float2 x2[NP][D_];
    __shared__ float smk[ROWS];

    const int j = threadIdx.x;
    const int row0 = blockIdx.x * ROWS;

    float hcur[ROWS], hlast[ROWS], seen[ROWS], hode[ROWS];
#pragma unroll
    for (int r = 0; r < ROWS; r++) { hcur[r] = 0.0f; hlast[r] = 0.0f; seen[r] = 0.0f; }
#pragma unroll
    for (int p = 0; p < NP; p++) h2[p][j] = make_float2(0.0f, 0.0f);

    const float b1j = b1[j];
    const float b2j = b2[j];
    const float bir = b_ih[j], biz = b_ih[H_ + j], bin_ = b_ih[2 * H_ + j];
    const float bhr = b_hh[j], bhz = b_hh[H_ + j], bhn = b_hh[2 * H_ + j];

    __syncthreads();

    for (int t = 0; t < T_; t++) {
        // ---- stage 1: stage x_t pairs and mask ----
        {
            int p = j >> 6, c = j & 63;
            float v0 = x[((size_t)(row0 + 2 * p) * T_ + t) * D_ + c];
            float v1 = x[((size_t)(row0 + 2 * p + 1) * T_ + t) * D_ + c];
            x2[p][c] = make_float2(v0, v1);
        }
        if (j < ROWS) smk[j] = mask[(size_t)(row0 + j) * T_ + t];
        __syncthreads();

        // ---- stage 2: a1 = tanh(h @ w1^T + b1) ----
        {
            unsigned long long acc[NP];
#pragma unroll
            for (int p = 0; p < NP; p++) acc[p] = dup2(b1j);
            GEMM_H(acc, g_w1p, h2);
#pragma unroll
            for (int p = 0; p < NP; p++) {
                float2 f = upk2(acc[p]);
                a12[p][j] = make_float2(tanhf(f.x), tanhf(f.y));
            }
        }
        __syncthreads();

        // ---- stage 3: f = a1 @ w2^T + b2 ; euler ; h_ode ----
        {
            unsigned long long acc[NP];
#pragma unroll
            for (int p = 0; p < NP; p++) acc[p] = dup2(b2j);
            GEMM_H(acc, g_w2p, a12);
            const float dtv = g_dt[t];
#pragma unroll
            for (int p = 0; p < NP; p++) {
                float2 f = upk2(acc[p]);
                int r0 = 2 * p, r1 = 2 * p + 1;
                float he0 = hcur[r0] + dtv * f.x;
                float he1 = hcur[r1] + dtv * f.y;
                hode[r0] = (seen[r0] > 0.0f) ? he0 : hcur[r0];
                hode[r1] = (seen[r1] > 0.0f) ? he1 : hcur[r1];
                ode2[p][j] = make_float2(hode[r0], hode[r1]);
            }
        }
        __syncthreads();

        // ---- stage 4: GRU gates + state update ----
        {
            unsigned long long ir[NP], iz[NP], inn[NP];
#pragma unroll
            for (int p = 0; p < NP; p++) { ir[p] = dup2(bir); iz[p] = dup2(biz); inn[p] = dup2(bin_); }
#pragma unroll 2
            for (int k4 = 0; k4 < D_ / 4; k4++) {
                float4 wr = g_wihp[k4 * (3 * H_) + j];
                float4 wz = g_wihp[k4 * (3 * H_) + H_ + j];
                float4 wn = g_wihp[k4 * (3 * H_) + 2 * H_ + j];
                unsigned long long wr0 = dup2(wr.x), wr1 = dup2(wr.y), wr2 = dup2(wr.z), wr3 = dup2(wr.w);
                unsigned long long wz0 = dup2(wz.x), wz1 = dup2(wz.y), wz2 = dup2(wz.z), wz3 = dup2(wz.w);
                unsigned long long wn0 = dup2(wn.x), wn1 = dup2(wn.y), wn2 = dup2(wn.z), wn3 = dup2(wn.w);
#pragma unroll
                for (int p = 0; p < NP; p++) {
                    ulonglong2 xA = *reinterpret_cast<const ulonglong2*>(&x2[p][4 * k4]);
                    ulonglong2 xB = *reinterpret_cast<const ulonglong2*>(&x2[p][4 * k4 + 2]);
                    ir[p] = ffma2(wr0, xA.x, ir[p]); ir[p] = ffma2(wr1, xA.y, ir[p]);
                    ir[p] = ffma2(wr2, xB.x, ir[p]); ir[p] = ffma2(wr3, xB.y, ir[p]);
                    iz[p] = ffma2(wz0, xA.x, iz[p]); iz[p] = ffma2(wz1, xA.y, iz[p]);
                    iz[p] = ffma2(wz2, xB.x, iz[p]); iz[p] = ffma2(wz3, xB.y, iz[p]);
                    inn[p] = ffma2(wn0, xA.x, inn[p]); inn[p] = ffma2(wn1, xA.y, inn[p]);
                    inn[p] = ffma2(wn2, xB.x, inn[p]); inn[p] = ffma2(wn3, xB.y, inn[p]);
                }
            }

            unsigned long long gr[NP], gz[NP], gn[NP];
#pragma unroll
            for (int p = 0; p < NP; p++) { gr[p] = dup2(bhr); gz[p] = dup2(bhz); gn[p] = dup2(bhn); }
#pragma unroll 2
            for (int k4 = 0; k4 < H_ / 4; k4++) {
                float4 wr = g_whhp[k4 * (3 * H_) + j];
                float4 wz = g_whhp[k4 * (3 * H_) + H_ + j];
                float4 wn = g_whhp[k4 * (3 * H_) + 2 * H_ + j];
                unsigned long long wr0 = dup2(wr.x), wr1 = dup2(wr.y), wr2 = dup2(wr.z), wr3 = dup2(wr.w);
                unsigned long long wz0 = dup2(wz.x), wz1 = dup2(wz.y), wz2 = dup2(wz.z), wz3 = dup2(wz.w);
                unsigned long long wn0 = dup2(wn.x), wn1 = dup2(wn.y), wn2 = dup2(wn.z), wn3 = dup2(wn.w);
#pragma unroll
                for (int p = 0; p < NP; p++) {
                    ulonglong2 oA = *reinterpret_cast<const ulonglong2*>(&ode2[p][4 * k4]);
                    ulonglong2 oB = *reinterpret_cast<const ulonglong2*>(&ode2[p][4 * k4 + 2]);
                    gr[p] = ffma2(wr0, oA.x, gr[p]); gr[p] = ffma2(wr1, oA.y, gr[p]);
                    gr[p] = ffma2(wr2, oB.x, gr[p]); gr[p] = ffma2(wr3, oB.y, gr[p]);
                    gz[p] = ffma2(wz0, oA.x, gz[p]); gz[p] = ffma2(wz1, oA.y, gz[p]);
                    gz[p] = ffma2(wz2, oB.x, gz[p]); gz[p] = ffma2(wz3, oB.y, gz[p]);
                    gn[p] = ffma2(wn0, oA.x, gn[p]); gn[p] = ffma2(wn1, oA.y, gn[p]);
                    gn[p] = ffma2(wn2, oB.x, gn[p]); gn[p] = ffma2(wn3, oB.y, gn[p]);
                }
            }

#pragma unroll
            for (int p = 0; p < NP; p++) {
                float2 fir = upk2(ir[p]), fiz = upk2(iz[p]), fin = upk2(inn[p]);
                float2 fgr = upk2(gr[p]), fgz = upk2(gz[p]), fgn = upk2(gn[p]);
                int r0 = 2 * p, r1 = 2 * p + 1;

                float rg0 = sigmoidf_(fir.x + fgr.x);
                float zg0 = sigmoidf_(fiz.x + fgz.x);
                float ng0 = tanhf(fin.x + rg0 * fgn.x);
                float hr0 = (1.0f - zg0) * ng0 + zg0 * hode[r0];
                float m0 = smk[r0];
                float hn0 = (m0 > 0.5f) ? hr0 : hode[r0];
                hcur[r0] = hn0;
                hlast[r0] = (m0 > 0.5f) ? hn0 : hlast[r0];
                seen[r0] = fmaxf(seen[r0], m0);

                float rg1 = sigmoidf_(fir.y + fgr.y);
                float zg1 = sigmoidf_(fiz.y + fgz.y);
                float ng1 = tanhf(fin.y + rg1 * fgn.y);
                float hr1 = (1.0f - zg1) * ng1 + zg1 * hode[r1];
                float m1 = smk[r1];
                float hn1 = (m1 > 0.5f) ? hr1 : hode[r1];
                hcur[r1] = hn1;
                hlast[r1] = (m1 > 0.5f) ? hn1 : hlast[r1];
                seen[r1] = fmaxf(seen[r1], m1);

                h2[p][j] = make_float2(hn0, hn1);
            }
        }
        __syncthreads();
    }

    // ---- final projection: out = h_last @ w_out^T + b_out ----
#pragma unroll
    for (int p = 0; p < NP; p++) h2[p][j] = make_float2(hlast[2 * p], hlast[2 * p + 1]);
    __syncthreads();

    {
        unsigned long long acc[NP];
        float bo = b_out[j];
#pragma unroll
        for (int p = 0; p < NP; p++) acc[p] = dup2(bo);
        GEMM_H(acc, g_woutp, h2);
#pragma unroll
        for (int p = 0; p < NP; p++) {
            float2 f = upk2(acc[p]);
            out[(size_t)(row0 + 2 * p) * H_ + j] = f.x;
            out[(size_t)(row0 + 2 * p + 1) * H_ + j] = f.y;
        }
    }
}

extern "C" void kernel_launch(void* const* d_in, const int* in_sizes, int n_in,
                              void* d_out, int out_size) {
    const float* x     = (const float*)d_in[0];
    const float* tps   = (const float*)d_in[1];
    const float* mask  = (const float*)d_in[2];
    const float* w_ih  = (const float*)d_in[3];
    const float* w_hh  = (const float*)d_in[4];
    const float* b_ih  = (const float*)d_in[5];
    const float* b_hh  = (const float*)d_in[6];
    const float* w1    = (const float*)d_in[7];
    const float* b1    = (const float*)d_in[8];
    const float* w2    = (const float*)d_in[9];
    const float* b2    = (const float*)d_in[10];
    const float* w_out = (const float*)d_in[11];
    const float* b_out = (const float*)d_in[12];
    float* out = (float*)d_out;

    pack_all_kernel<<<(PK_TOTAL + 255) / 256, 256>>>(w1, w2, w_hh, w_ih, w_out, tps);
    gruode_kernel<<<NCTA, H_>>>(x, mask, b_ih, b_hh, b1, b2, b_out, out);
}

// round 5
// speedup vs baseline: 3.2810x; 1.8794x over previous
#include <cuda_runtime.h>
#include <cstdint>

#define T_ 256
#define D_ 64
#define H_ 256
#define B_ 512
#define ROWSC 8
#define NPC 4
#define JH 128
#define NCTA 128
#define THREADS 512

// packed: P[k4 * O + o] = float4{ W[o][4k4+0..3] }
__device__ float4 g_w1p[(H_ / 4) * H_];
__device__ float4 g_w2p[(H_ / 4) * H_];
__device__ float4 g_whhp[(H_ / 4) * (3 * H_)];
__device__ float4 g_wihp[(D_ / 4) * (3 * H_)];
__device__ float4 g_woutp[(H_ / 4) * H_];
__device__ float g_dt[T_];

#define N_W1 ((H_ / 4) * H_)
#define N_WHH ((H_ / 4) * (3 * H_))
#define N_WIH ((D_ / 4) * (3 * H_))
#define PK_TOTAL (3 * N_W1 + N_WHH + N_WIH)

__global__ void pack_all_kernel(const float* __restrict__ w1,
                                const float* __restrict__ w2,
                                const float* __restrict__ whh,
                                const float* __restrict__ wih,
                                const float* __restrict__ wout,
                                const float* __restrict__ tps) {
    int idx = blockIdx.x * blockDim.x + threadIdx.x;
    if (idx < T_) {
        g_dt[idx] = (idx == 0) ? (tps[0] - (tps[0] - 0.01f))
                               : (tps[idx] - tps[idx - 1]);
    }
    if (idx >= PK_TOTAL) return;
    const float* src; float4* dst; int O, K, local = idx;
    if (local < N_W1) { src = w1; dst = g_w1p; O = H_; K = H_; }
    else if ((local -= N_W1) < N_W1) { src = w2; dst = g_w2p; O = H_; K = H_; }
    else if ((local -= N_W1) < N_WHH) { src = whh; dst = g_whhp; O = 3 * H_; K = H_; }
    else if ((local -= N_WHH) < N_WIH) { src = wih; dst = g_wihp; O = 3 * H_; K = D_; }
    else { local -= N_WIH; src = wout; dst = g_woutp; O = H_; K = H_; }
    int k4 = local / O;
    int o = local % O;
    const float* s = src + (size_t)o * K + 4 * k4;
    dst[local] = make_float4(s[0], s[1], s[2], s[3]);
}

typedef unsigned long long ull;
__device__ __forceinline__ ull pk2(float a, float b) {
    ull r; asm("mov.b64 %0, {%1, %2};" : "=l"(r) : "f"(a), "f"(b)); return r;
}
__device__ __forceinline__ ull dup2(float a) { return pk2(a, a); }
__device__ __forceinline__ ull ffma2(ull a, ull b, ull c) {
    ull d; asm("fma.rn.f32x2 %0, %1, %2, %3;" : "=l"(d) : "l"(a), "l"(b), "l"(c)); return d;
}
__device__ __forceinline__ ull add2(ull a, ull b) {
    ull d; asm("add.rn.f32x2 %0, %1, %2;" : "=l"(d) : "l"(a), "l"(b)); return d;
}
__device__ __forceinline__ float2 upk2(ull v) {
    float2 f; asm("mov.b64 {%0, %1}, %2;" : "=f"(f.x), "=f"(f.y) : "l"(v)); return f;
}
__device__ __forceinline__ float sigmoidf_(float v) { return 1.0f / (1.0f + expf(-v)); }
__device__ __forceinline__ uint32_t smem_u32(const void* p) {
    return (uint32_t)__cvta_generic_to_shared(p);
}
__device__ __forceinline__ void sts_peer_u64(const void* laddr, uint32_t peer, ull v) {
    uint32_t la = smem_u32(laddr), ra;
    asm("mapa.shared::cluster.u32 %0, %1, %2;" : "=r"(ra) : "r"(la), "r"(peer));
    asm volatile("st.shared::cluster.u64 [%0], %1;" :: "r"(ra), "l"(v) : "memory");
}
__device__ __forceinline__ void cluster_sync_() {
    asm volatile("barrier.cluster.arrive.aligned;" ::: "memory");
    asm volatile("barrier.cluster.wait.aligned;" ::: "memory");
}

#define GEMM_HALF(ACC, WP, BUF, KBASE)                                         \
    _Pragma("unroll 4")                                                        \
    for (int kk = 0; kk < 32; kk++) {                                          \
        int k4 = (KBASE) + kk;                                                 \
        float4 w = (WP)[k4 * H_ + jg];                                         \
        ull w0 = dup2(w.x), w1d = dup2(w.y), w2d = dup2(w.z), w3d = dup2(w.w); \
        _Pragma("unroll")                                                      \
        for (int pp = 0; pp < 2; pp++) {                                       \
            int p = 2 * pg + pp;                                               \
            ulonglong2 hA = *reinterpret_cast<const ulonglong2*>(&(BUF)[p][4 * k4]);     \
            ulonglong2 hB = *reinterpret_cast<const ulonglong2*>(&(BUF)[p][4 * k4 + 2]); \
            (ACC)[pp] = ffma2(w0, hA.x, (ACC)[pp]);                            \
            (ACC)[pp] = ffma2(w1d, hA.y, (ACC)[pp]);                           \
            (ACC)[pp] = ffma2(w2d, hB.x, (ACC)[pp]);                           \
            (ACC)[pp] = ffma2(w3d, hB.y, (ACC)[pp]);                           \
        }                                                                      \
    }

__global__ void __launch_bounds__(THREADS, 1) __cluster_dims__(2, 1, 1)
gruode_kernel(const float* __restrict__ x,
              const float* __restrict__ mask,
              const float* __restrict__ b_ih,
              const float* __restrict__ b_hh,
              const float* __restrict__ b1,
              const float* __restrict__ b2,
              const float* __restrict__ b_out,
              float* __restrict__ out) {
    __shared__ __align__(16) float2 h2[NPC][H_];
    __shared__ __align__(16) float2 ode2[NPC][H_];
    __shared__ __align__(16) float2 a12[NPC][H_];
    __shared__ __align__(16) float2 x2[NPC][D_];
    __shared__ float smk[ROWSC];
    __shared__ ulonglong2 partA[2][JH];
    __shared__ ulonglong2 partGr[2][JH];
    __shared__ ulonglong2 partGz[2][JH];
    __shared__ ulonglong2 partGn[2][JH];

    const int tid = threadIdx.x;
    const int j0 = tid & (JH - 1);
    const int kh = (tid >> 7) & 1;
    const int pg = (tid >> 8) & 1;
    uint32_t rank;
    asm("mov.u32 %0, %%cluster_ctarank;" : "=r"(rank));
    const uint32_t peer = rank ^ 1u;
    const int jg = (int)rank * JH + j0;
    const int row0 = (blockIdx.x >> 1) * ROWSC;
    const int kb = kh * 32;
    const int kbx = kh * 8;

    for (int idx = tid; idx < NPC * H_; idx += THREADS)
        (&h2[0][0])[idx] = make_float2(0.0f, 0.0f);

    float hcur[4], hlast[4], seen[4], hode[4];
#pragma unroll
    for (int r = 0; r < 4; r++) { hcur[r] = 0.0f; hlast[r] = 0.0f; seen[r] = 0.0f; }

    const float b1j = b1[jg];
    const float b2j = b2[jg];
    const float bir = b_ih[jg], biz = b_ih[H_ + jg], bin_ = b_ih[2 * H_ + jg];
    const float bhr = b_hh[jg], bhz = b_hh[H_ + jg], bhn = b_hh[2 * H_ + jg];
    // fused gate biases (r and z gates sum gi+gh before sigmoid)
    const float brz_r = bir + bhr;
    const float brz_z = biz + bhz;

    cluster_sync_();

    for (int t = 0; t < T_; t++) {
        // ---- stage 1: x_t + mask (CTA-local full copies) ----
        if (tid < NPC * D_) {
            int p = tid >> 6, c = tid & 63;
            float v0 = x[((size_t)(row0 + 2 * p) * T_ + t) * D_ + c];
            float v1 = x[((size_t)(row0 + 2 * p + 1) * T_ + t) * D_ + c];
            x2[p][c] = make_float2(v0, v1);
        }
        if (tid < ROWSC) smk[tid] = mask[(size_t)(row0 + tid) * T_ + t];

        // ---- stage 2: a1 = tanh(h @ w1^T + b1) ----
        {
            ull acc[2];
            acc[0] = acc[1] = (kh == 0) ? dup2(b1j) : 0ull;
            GEMM_HALF(acc, g_w1p, h2, kb);
            if (kh == 1) partA[pg][j0] = make_ulonglong2(acc[0], acc[1]);
            __syncthreads();
            if (kh == 0) {
                ulonglong2 o = partA[pg][j0];
                float2 f0 = upk2(add2(acc[0], o.x));
                float2 f1 = upk2(add2(acc[1], o.y));
                float2 r0 = make_float2(tanhf(f0.x), tanhf(f0.y));
                float2 r1 = make_float2(tanhf(f1.x), tanhf(f1.y));
                a12[2 * pg][jg] = r0;
                a12[2 * pg + 1][jg] = r1;
                sts_peer_u64(&a12[2 * pg][jg], peer, pk2(r0.x, r0.y));
                sts_peer_u64(&a12[2 * pg + 1][jg], peer, pk2(r1.x, r1.y));
            }
        }
        cluster_sync_();

        // ---- stage 3: h_ode ----
        {
            ull acc[2];
            acc[0] = acc[1] = (kh == 0) ? dup2(b2j) : 0ull;
            GEMM_HALF(acc, g_w2p, a12, kb);
            if (kh == 1) partA[pg][j0] = make_ulonglong2(acc[0], acc[1]);
            __syncthreads();
            if (kh == 0) {
                ulonglong2 o = partA[pg][j0];
                const float dtv = g_dt[t];
                float2 f0 = upk2(add2(acc[0], o.x));
                float2 f1 = upk2(add2(acc[1], o.y));
                float fv[4] = { f0.x, f0.y, f1.x, f1.y };
#pragma unroll
                for (int pp = 0; pp < 2; pp++) {
                    int i0 = 2 * pp, i1 = 2 * pp + 1;
                    float he0 = hcur[i0] + dtv * fv[i0];
                    float he1 = hcur[i1] + dtv * fv[i1];
                    hode[i0] = (seen[i0] > 0.0f) ? he0 : hcur[i0];
                    hode[i1] = (seen[i1] > 0.0f) ? he1 : hcur[i1];
                    float2 ov = make_float2(hode[i0], hode[i1]);
                    ode2[2 * pg + pp][jg] = ov;
                    sts_peer_u64(&ode2[2 * pg + pp][jg], peer, pk2(ov.x, ov.y));
                }
            }
        }
        cluster_sync_();

        // ---- stage 4: gates ----
        {
            // r/z gates: gi+gh fused (both biases!); n-gate: gi_n and gh_n separate
            ull ar[2], az[2], an[2], in_[2];
            ar[0] = ar[1] = (kh == 0) ? dup2(brz_r) : 0ull;
            az[0] = az[1] = (kh == 0) ? dup2(brz_z) : 0ull;
            an[0] = an[1] = (kh == 0) ? dup2(bhn) : 0ull;
            in_[0] = in_[1] = (kh == 0) ? dup2(bin_) : 0ull;

#pragma unroll
            for (int kk = 0; kk < 8; kk++) {
                int k4 = kbx + kk;
                float4 wr = g_wihp[k4 * (3 * H_) + jg];
                float4 wz = g_wihp[k4 * (3 * H_) + H_ + jg];
                float4 wn = g_wihp[k4 * (3 * H_) + 2 * H_ + jg];
                ull wr0 = dup2(wr.x), wr1 = dup2(wr.y), wr2 = dup2(wr.z), wr3 = dup2(wr.w);
                ull wz0 = dup2(wz.x), wz1 = dup2(wz.y), wz2 = dup2(wz.z), wz3 = dup2(wz.w);
                ull wn0 = dup2(wn.x), wn1 = dup2(wn.y), wn2 = dup2(wn.z), wn3 = dup2(wn.w);
#pragma unroll
                for (int pp = 0; pp < 2; pp++) {
                    int p = 2 * pg + pp;
                    ulonglong2 xA = *reinterpret_cast<const ulonglong2*>(&x2[p][4 * k4]);
                    ulonglong2 xB = *reinterpret_cast<const ulonglong2*>(&x2[p][4 * k4 + 2]);
                    ar[pp] = ffma2(wr0, xA.x, ar[pp]); ar[pp] = ffma2(wr1, xA.y, ar[pp]);
                    ar[pp] = ffma2(wr2, xB.x, ar[pp]); ar[pp] = ffma2(wr3, xB.y, ar[pp]);
                    az[pp] = ffma2(wz0, xA.x, az[pp]); az[pp] = ffma2(wz1, xA.y, az[pp]);
                    az[pp] = ffma2(wz2, xB.x, az[pp]); az[pp] = ffma2(wz3, xB.y, az[pp]);
                    in_[pp] = ffma2(wn0, xA.x, in_[pp]); in_[pp] = ffma2(wn1, xA.y, in_[pp]);
                    in_[pp] = ffma2(wn2, xB.x, in_[pp]); in_[pp] = ffma2(wn3, xB.y, in_[pp]);
                }
            }
#pragma unroll 2
            for (int kk = 0; kk < 32; kk++) {
                int k4 = kb + kk;
                float4 wr = g_whhp[k4 * (3 * H_) + jg];
                float4 wz = g_whhp[k4 * (3 * H_) + H_ + jg];
                float4 wn = g_whhp[k4 * (3 * H_) + 2 * H_ + jg];
                ull wr0 = dup2(wr.x), wr1 = dup2(wr.y), wr2 = dup2(wr.z), wr3 = dup2(wr.w);
                ull wz0 = dup2(wz.x), wz1 = dup2(wz.y), wz2 = dup2(wz.z), wz3 = dup2(wz.w);
                ull wn0 = dup2(wn.x), wn1 = dup2(wn.y), wn2 = dup2(wn.z), wn3 = dup2(wn.w);
#pragma unroll
                for (int pp = 0; pp < 2; pp++) {
                    int p = 2 * pg + pp;
                    ulonglong2 oA = *reinterpret_cast<const ulonglong2*>(&ode2[p][4 * k4]);
                    ulonglong2 oB = *reinterpret_cast<const ulonglong2*>(&ode2[p][4 * k4 + 2]);
                    ar[pp] = ffma2(wr0, oA.x, ar[pp]); ar[pp] = ffma2(wr1, oA.y, ar[pp]);
                    ar[pp] = ffma2(wr2, oB.x, ar[pp]); ar[pp] = ffma2(wr3, oB.y, ar[pp]);
                    az[pp] = ffma2(wz0, oA.x, az[pp]); az[pp] = ffma2(wz1, oA.y, az[pp]);
                    az[pp] = ffma2(wz2, oB.x, az[pp]); az[pp] = ffma2(wz3, oB.y, az[pp]);
                    an[pp] = ffma2(wn0, oA.x, an[pp]); an[pp] = ffma2(wn1, oA.y, an[pp]);
                    an[pp] = ffma2(wn2, oB.x, an[pp]); an[pp] = ffma2(wn3, oB.y, an[pp]);
                }
            }

            if (kh == 1) {
                partGr[pg][j0] = make_ulonglong2(ar[0], ar[1]);
                partGz[pg][j0] = make_ulonglong2(az[0], az[1]);
                partGn[pg][j0] = make_ulonglong2(an[0], an[1]);
                partA[pg][j0] = make_ulonglong2(in_[0], in_[1]);
            }
            __syncthreads();
            if (kh == 0) {
                ulonglong2 pr = partGr[pg][j0];
                ulonglong2 pz = partGz[pg][j0];
                ulonglong2 pn = partGn[pg][j0];
                ulonglong2 pi = partA[pg][j0];
                float2 fr[2], fz[2], fgn[2], fin[2];
                fr[0] = upk2(add2(ar[0], pr.x)); fr[1] = upk2(add2(ar[1], pr.y));
                fz[0] = upk2(add2(az[0], pz.x)); fz[1] = upk2(add2(az[1], pz.y));
                fgn[0] = upk2(add2(an[0], pn.x)); fgn[1] = upk2(add2(an[1], pn.y));
                fin[0] = upk2(add2(in_[0], pi.x)); fin[1] = upk2(add2(in_[1], pi.y));
#pragma unroll
                for (int pp = 0; pp < 2; pp++) {
                    int i0 = 2 * pp, i1 = 2 * pp + 1;
                    float rg0 = sigmoidf_(fr[pp].x);
                    float zg0 = sigmoidf_(fz[pp].x);
                    float ng0 = tanhf(fin[pp].x + rg0 * fgn[pp].x);
                    float hr0 = (1.0f - zg0) * ng0 + zg0 * hode[i0];
                    float m0 = smk[4 * pg + 2 * pp];
                    float hn0 = (m0 > 0.5f) ? hr0 : hode[i0];
                    hcur[i0] = hn0;
                    hlast[i0] = (m0 > 0.5f) ? hn0 : hlast[i0];
                    seen[i0] = fmaxf(seen[i0], m0);

                    float rg1 = sigmoidf_(fr[pp].y);
                    float zg1 = sigmoidf_(fz[pp].y);
                    float ng1 = tanhf(fin[pp].y + rg1 * fgn[pp].y);
                    float hr1 = (1.0f - zg1) * ng1 + zg1 * hode[i1];
                    float m1 = smk[4 * pg + 2 * pp + 1];
                    float hn1 = (m1 > 0.5f) ? hr1 : hode[i1];
                    hcur[i1] = hn1;
                    hlast[i1] = (m1 > 0.5f) ? hn1 : hlast[i1];
                    seen[i1] = fmaxf(seen[i1], m1);

                    float2 hv = make_float2(hn0, hn1);
                    h2[2 * pg + pp][jg] = hv;
                    sts_peer_u64(&h2[2 * pg + pp][jg], peer, pk2(hv.x, hv.y));
                }
            }
        }
        cluster_sync_();
    }

    // ---- final projection: out = h_last @ w_out^T + b_out ----
    if (kh == 0) {
#pragma unroll
        for (int pp = 0; pp < 2; pp++) {
            float2 hv = make_float2(hlast[2 * pp], hlast[2 * pp + 1]);
            h2[2 * pg + pp][jg] = hv;
            sts_peer_u64(&h2[2 * pg + pp][jg], peer, pk2(hv.x, hv.y));
        }
    }
    cluster_sync_();
    {
        const float boj = b_out[jg];
        ull acc[2];
        acc[0] = acc[1] = (kh == 0) ? dup2(boj) : 0ull;
        GEMM_HALF(acc, g_woutp, h2, kb);
        if (kh == 1) partA[pg][j0] = make_ulonglong2(acc[0], acc[1]);
        __syncthreads();
        if (kh == 0) {
            ulonglong2 o = partA[pg][j0];
            float2 f0 = upk2(add2(acc[0], o.x));
            float2 f1 = upk2(add2(acc[1], o.y));
            out[(size_t)(row0 + 4 * pg + 0) * H_ + jg] = f0.x;
            out[(size_t)(row0 + 4 * pg + 1) * H_ + jg] = f0.y;
            out[(size_t)(row0 + 4 * pg + 2) * H_ + jg] = f1.x;
            out[(size_t)(row0 + 4 * pg + 3) * H_ + jg] = f1.y;
        }
    }
    cluster_sync_();
}

extern "C" void kernel_launch(void* const* d_in, const int* in_sizes, int n_in,
                              void* d_out, int out_size) {
    const float* x     = (const float*)d_in[0];
    const float* tps   = (const float*)d_in[1];
    const float* mask  = (const float*)d_in[2];
    const float* w_ih  = (const float*)d_in[3];
    const float* w_hh  = (const float*)d_in[4];
    const float* b_ih  = (const float*)d_in[5];
    const float* b_hh  = (const float*)d_in[6];
    const float* w1    = (const float*)d_in[7];
    const float* b1    = (const float*)d_in[8];
    const float* w2    = (const float*)d_in[9];
    const float* b2    = (const float*)d_in[10];
    const float* w_out = (const float*)d_in[11];
    const float* b_out = (const float*)d_in[12];
    float* out = (float*)d_out;

    pack_all_kernel<<<(PK_TOTAL + 255) / 256, 256>>>(w1, w2, w_hh, w_ih, w_out, tps);
    gruode_kernel<<<NCTA, THREADS>>>(x, mask, b_ih, b_hh, b1, b2, b_out, out);
}